// round 2
// baseline (speedup 1.0000x reference)
#include <cuda_runtime.h>
#include <cstdint>
#include <cstdio>

#define N_NODES 100000
#define N_EDGES 1600000
#define IN_DIM 1433
#define HID_DIM 128
#define EMB_DIM 64

// ---------------- scratch (static device globals; no cudaMalloc allowed) ----------------
__device__ float g_g1[(size_t)N_NODES * HID_DIM];   // (x@W1) * dinv[row]
__device__ float g_h1[(size_t)N_NODES * HID_DIM];   // relu(layer1)
__device__ float g_g2[(size_t)N_NODES * EMB_DIM];   // (h1@W2) * dinv[row]
__device__ int   g_indeg[N_NODES];
__device__ int   g_rowptr[N_NODES + 1];
__device__ int   g_cursor[N_NODES];
__device__ int   g_col[N_EDGES];
__device__ float g_dinv[N_NODES];

// ---------------- CSR build ----------------
__global__ void k_zero_indeg() {
    int i = blockIdx.x * blockDim.x + threadIdx.x;
    if (i < N_NODES) g_indeg[i] = 0;
}

__global__ void k_hist(const int* __restrict__ dst) {
    int e = blockIdx.x * blockDim.x + threadIdx.x;
    if (e < N_EDGES) atomicAdd(&g_indeg[dst[e]], 1);
}

// Single-block chunked exclusive scan over indeg -> rowptr, cursor, dinv.
__global__ void k_scan() {
    __shared__ int s[1024];
    int tid = threadIdx.x;
    int carry = 0;
    for (int base = 0; base < N_NODES; base += 1024) {
        int i = base + tid;
        int v = (i < N_NODES) ? g_indeg[i] : 0;
        s[tid] = v;
        __syncthreads();
        #pragma unroll
        for (int off = 1; off < 1024; off <<= 1) {
            int t = (tid >= off) ? s[tid - off] : 0;
            __syncthreads();
            s[tid] += t;
            __syncthreads();
        }
        int incl = s[tid];
        int excl = incl - v;
        if (i < N_NODES) {
            int rp = carry + excl;
            g_rowptr[i] = rp;
            g_cursor[i] = rp;
            g_dinv[i]   = rsqrtf((float)(v + 1));  // +1 self loop; always > 0
        }
        carry += s[1023];
        __syncthreads();
    }
    if (tid == 0) g_rowptr[N_NODES] = N_EDGES;
}

__global__ void k_fill(const int* __restrict__ src, const int* __restrict__ dst) {
    int e = blockIdx.x * blockDim.x + threadIdx.x;
    if (e < N_EDGES) {
        int pos = atomicAdd(&g_cursor[dst[e]], 1);
        g_col[pos] = src[e];
    }
}

// ---------------- tiled fp32 GEMM with dinv-scaled epilogue ----------------
// C[M x BN] = (A[M x K] @ B[K x BN]) * dinv[row]
// BM=128, BK=16, micro-tile 8x8. N of the problem == BN (single block column).
template <int BN>
__global__ __launch_bounds__(16 * (BN / 8))
void gemm_dinv_kernel(const float* __restrict__ A, const float* __restrict__ B,
                      float* __restrict__ C, int M, int K) {
    constexpr int BM = 128, BK = 16, TM = 8, TN = 8;
    constexpr int TX = BN / TN;          // 16 or 8
    constexpr int TY = BM / TM;          // 16
    constexpr int NT = TX * TY;          // 256 or 128

    __shared__ float As[BK][BM + 4];
    __shared__ float Bs[BK][BN];

    const int tid = threadIdx.x;
    const int block_row = blockIdx.x * BM;
    const int tx = tid % TX;
    const int ty = tid / TX;

    float acc[TM][TN] = {};

    for (int k0 = 0; k0 < K; k0 += BK) {
        // load A tile (BM x BK), transpose into As[k][m]
        #pragma unroll
        for (int idx = tid; idx < BM * BK; idx += NT) {
            int r = idx / BK, c = idx % BK;
            int gr = block_row + r, gc = k0 + c;
            float v = 0.f;
            if (gr < M && gc < K) v = A[(size_t)gr * K + gc];
            As[c][r] = v;
        }
        // load B tile (BK x BN)
        #pragma unroll
        for (int idx = tid; idx < BK * BN; idx += NT) {
            int r = idx / BN, c = idx % BN;
            int gr = k0 + r;
            Bs[r][c] = (gr < K) ? B[(size_t)gr * BN + c] : 0.f;
        }
        __syncthreads();

        #pragma unroll
        for (int k = 0; k < BK; k++) {
            float ra[TM], rb[TN];
            #pragma unroll
            for (int i = 0; i < TM; i++) ra[i] = As[k][ty * TM + i];
            #pragma unroll
            for (int j = 0; j < TN; j++) rb[j] = Bs[k][tx * TN + j];
            #pragma unroll
            for (int i = 0; i < TM; i++)
                #pragma unroll
                for (int j = 0; j < TN; j++)
                    acc[i][j] = fmaf(ra[i], rb[j], acc[i][j]);
        }
        __syncthreads();
    }

    #pragma unroll
    for (int i = 0; i < TM; i++) {
        int gr = block_row + ty * TM + i;
        if (gr < M) {
            float s = g_dinv[gr];
            #pragma unroll
            for (int j = 0; j < TN; j++)
                C[(size_t)gr * BN + tx * TN + j] = acc[i][j] * s;
        }
    }
}

// ---------------- CSR gather aggregation ----------------
// out[i,f] = act( dinv[i] * ( sum_{j in N(i)} g[j,f] + g[i,f] ) + bias[f] )
template <int F, bool RELU>
__global__ __launch_bounds__(F)
void aggregate_kernel(const float* __restrict__ g, const float* __restrict__ bias,
                      float* __restrict__ out) {
    int node = blockIdx.x;
    int f = threadIdx.x;
    int start = g_rowptr[node];
    int end   = g_rowptr[node + 1];
    float s = g[(size_t)node * F + f];        // self loop
    for (int e = start; e < end; e++) {
        int src = g_col[e];
        s += __ldg(&g[(size_t)src * F + f]);
    }
    float v = g_dinv[node] * s + bias[f];
    if (RELU) v = fmaxf(v, 0.f);
    out[(size_t)node * F + f] = v;
}

// ---------------- launch ----------------
extern "C" void kernel_launch(void* const* d_in, const int* in_sizes, int n_in,
                              void* d_out, int out_size) {
    const float* x  = (const float*)d_in[0];
    const int*   ei = (const int*)  d_in[1];
    const float* W1 = (const float*)d_in[2];
    const float* b1 = (const float*)d_in[3];
    const float* W2 = (const float*)d_in[4];
    const float* b2 = (const float*)d_in[5];
    float* out = (float*)d_out;

    const int* src = ei;
    const int* dst = ei + N_EDGES;

    float *p_g1 = nullptr, *p_h1 = nullptr, *p_g2 = nullptr;
    cudaGetSymbolAddress((void**)&p_g1, g_g1);
    cudaGetSymbolAddress((void**)&p_h1, g_h1);
    cudaGetSymbolAddress((void**)&p_g2, g_g2);

    // CSR build + degrees
    k_zero_indeg<<<(N_NODES + 255) / 256, 256>>>();
    k_hist<<<(N_EDGES + 511) / 512, 512>>>(dst);
    k_scan<<<1, 1024>>>();
    k_fill<<<(N_EDGES + 511) / 512, 512>>>(src, dst);

    const int mblocks = (N_NODES + 127) / 128;

    // layer 1: g1 = (x @ W1) * dinv ; h1 = relu(dinv * (gather-sum g1) + b1)
    gemm_dinv_kernel<HID_DIM><<<mblocks, 256>>>(x, W1, p_g1, N_NODES, IN_DIM);
    aggregate_kernel<HID_DIM, true><<<N_NODES, HID_DIM>>>(p_g1, b1, p_h1);

    // layer 2: g2 = (h1 @ W2) * dinv ; out = dinv * (gather-sum g2) + b2
    gemm_dinv_kernel<EMB_DIM><<<mblocks, 128>>>(p_h1, W2, p_g2, N_NODES, HID_DIM);
    aggregate_kernel<EMB_DIM, false><<<N_NODES, EMB_DIM>>>(p_g2, b2, out);
}

// round 4
// speedup vs baseline: 1.1682x; 1.1682x over previous
#include <cuda_runtime.h>
#include <cuda_bf16.h>
#include <cstdint>

#define N_NODES 100000
#define N_EDGES 1600000
#define IN_DIM 1433
#define HID_DIM 128
#define EMB_DIM 64
#define KPAD 1472          // 23 * 64
#define KCHUNKS 23

// ---------------- scratch (static device globals; no cudaMalloc allowed) ----------------
__device__ float g_g1[(size_t)N_NODES * HID_DIM];
__device__ float g_h1[(size_t)N_NODES * HID_DIM];
__device__ float g_g2[(size_t)N_NODES * EMB_DIM];
__device__ int   g_indeg[N_NODES];
__device__ int   g_rowptr[N_NODES + 1];
__device__ int   g_cursor[N_NODES];
__device__ int   g_col[N_EDGES];
__device__ float g_dinv[N_NODES];
__device__ __nv_bfloat16 g_Wt_hi[HID_DIM * KPAD];  // W1^T split-high, [128][KPAD]
__device__ __nv_bfloat16 g_Wt_lo[HID_DIM * KPAD];  // W1^T split-low

// ---------------- portable PTX helpers ----------------
__device__ __forceinline__ uint32_t smem_u32(const void* p) {
    uint32_t a;
    asm("{ .reg .u64 t; cvta.to.shared.u64 t, %1; cvt.u32.u64 %0, t; }" : "=r"(a) : "l"(p));
    return a;
}
__device__ __forceinline__ void ldsm_x4(uint32_t& r0, uint32_t& r1, uint32_t& r2, uint32_t& r3,
                                        uint32_t addr) {
    asm volatile("ldmatrix.sync.aligned.m8n8.x4.shared.b16 {%0,%1,%2,%3}, [%4];"
                 : "=r"(r0), "=r"(r1), "=r"(r2), "=r"(r3) : "r"(addr));
}
__device__ __forceinline__ void mma_bf16(float* d, const uint32_t* a, const uint32_t* b) {
    asm volatile(
        "mma.sync.aligned.m16n8k16.row.col.f32.bf16.bf16.f32 "
        "{%0,%1,%2,%3}, {%4,%5,%6,%7}, {%8,%9}, {%0,%1,%2,%3};"
        : "+f"(d[0]), "+f"(d[1]), "+f"(d[2]), "+f"(d[3])
        : "r"(a[0]), "r"(a[1]), "r"(a[2]), "r"(a[3]), "r"(b[0]), "r"(b[1]));
}

// ---------------- CSR build ----------------
__global__ void k_zero_indeg() {
    int i = blockIdx.x * blockDim.x + threadIdx.x;
    if (i < N_NODES) g_indeg[i] = 0;
}
__global__ void k_hist(const int* __restrict__ dst) {
    int e = blockIdx.x * blockDim.x + threadIdx.x;
    if (e < N_EDGES) atomicAdd(&g_indeg[dst[e]], 1);
}
__global__ void k_scan() {
    __shared__ int s[1024];
    int tid = threadIdx.x;
    int carry = 0;
    for (int base = 0; base < N_NODES; base += 1024) {
        int i = base + tid;
        int v = (i < N_NODES) ? g_indeg[i] : 0;
        s[tid] = v;
        __syncthreads();
        #pragma unroll
        for (int off = 1; off < 1024; off <<= 1) {
            int t = (tid >= off) ? s[tid - off] : 0;
            __syncthreads();
            s[tid] += t;
            __syncthreads();
        }
        int incl = s[tid];
        if (i < N_NODES) {
            int rp = carry + incl - v;
            g_rowptr[i] = rp;
            g_cursor[i] = rp;
            g_dinv[i]   = rsqrtf((float)(v + 1));
        }
        carry += s[1023];
        __syncthreads();
    }
    if (tid == 0) g_rowptr[N_NODES] = N_EDGES;
}
__global__ void k_fill(const int* __restrict__ src, const int* __restrict__ dst) {
    int e = blockIdx.x * blockDim.x + threadIdx.x;
    if (e < N_EDGES) {
        int pos = atomicAdd(&g_cursor[dst[e]], 1);
        g_col[pos] = src[e];
    }
}

// ---------------- W1 transpose + bf16 split ----------------
__global__ void k_convert_W(const float* __restrict__ W1) {
    int idx = blockIdx.x * blockDim.x + threadIdx.x;
    if (idx < HID_DIM * KPAD) {
        int n = idx / KPAD, k = idx % KPAD;
        float v = (k < IN_DIM) ? W1[(size_t)k * HID_DIM + n] : 0.f;
        __nv_bfloat16 h = __float2bfloat16(v);
        g_Wt_hi[idx] = h;
        g_Wt_lo[idx] = __float2bfloat16(v - __bfloat162float(h));
    }
}

// ---------------- HMMA GEMM1: C[M x 128] = (X @ W1) * dinv[row] ----------------
// 128x128 CTA tile, BK=64, 8 warps (2 x 4), warp tile 64x32,
// bf16 split: acc += Ah*Bh + Ah*Bl + Al*Bh  (fp32 accum)
#define SM_STRIDE 72   // bf16 elems per row (144B): conflict-free ldmatrix
__global__ __launch_bounds__(256)
void gemm1_hmma(const float* __restrict__ X, float* __restrict__ C) {
    extern __shared__ char smem[];
    const uint32_t AH = 0, AL = 128 * SM_STRIDE * 2,
                   BH = 2 * 128 * SM_STRIDE * 2, BL = 3 * 128 * SM_STRIDE * 2;
    const uint32_t sbase = smem_u32(smem);

    const int tid = threadIdx.x, lane = tid & 31, wid = tid >> 5;
    const int wm = wid >> 2;      // 0..1 -> 64-row slab
    const int wn = wid & 3;       // 0..3 -> 32-col slab
    const int mbase = blockIdx.x * 128;

    // ldmatrix lane addressing (element offsets, x stride SM_STRIDE)
    // A tile (16x16 at m0,kk): row = m0 + (lane&15), col = kk + ((lane&16)>>1)
    const int a_r = (lane & 15), a_c = ((lane & 16) >> 1);
    // B pair (two 8-col n-tiles x k16): row = n0 + ((lane&16)>>1) + (lane&7), col = kk + (lane&8)
    const int b_r = ((lane & 16) >> 1) + (lane & 7), b_c = (lane & 8);

    float acc[4][4][4];
    #pragma unroll
    for (int i = 0; i < 4; i++)
        #pragma unroll
        for (int j = 0; j < 4; j++)
            #pragma unroll
            for (int v = 0; v < 4; v++) acc[i][j][v] = 0.f;

    const uint32_t* __restrict__ bh32 = (const uint32_t*)g_Wt_hi;
    const uint32_t* __restrict__ bl32 = (const uint32_t*)g_Wt_lo;

    for (int kc = 0; kc < KCHUNKS; kc++) {
        const int k0 = kc * 64;
        __syncthreads();
        // --- A tile: 128 rows x 64 k, fp32 -> hi/lo bf16 ---
        #pragma unroll 4
        for (int p = tid; p < 128 * 32; p += 256) {
            int r = p >> 5, kp = p & 31;
            int gr = mbase + r, gk = k0 + kp * 2;
            float x0 = 0.f, x1 = 0.f;
            if (gr < N_NODES) {
                const float* row = X + (size_t)gr * IN_DIM;
                if (gk < IN_DIM)     x0 = __ldg(row + gk);
                if (gk + 1 < IN_DIM) x1 = __ldg(row + gk + 1);
            }
            __nv_bfloat16 h0 = __float2bfloat16(x0), h1 = __float2bfloat16(x1);
            __nv_bfloat16 l0 = __float2bfloat16(x0 - __bfloat162float(h0));
            __nv_bfloat16 l1 = __float2bfloat16(x1 - __bfloat162float(h1));
            uint32_t off = (uint32_t)(r * SM_STRIDE + kp * 2) * 2;
            __nv_bfloat162 hv; hv.x = h0; hv.y = h1;
            __nv_bfloat162 lv; lv.x = l0; lv.y = l1;
            *(__nv_bfloat162*)(smem + AH + off) = hv;
            *(__nv_bfloat162*)(smem + AL + off) = lv;
        }
        // --- B tile: 128 n-rows x 64 k (already bf16, [n][KPAD]) ---
        #pragma unroll 4
        for (int p = tid; p < 128 * 32; p += 256) {
            int n = p >> 5, kp = p & 31;
            uint32_t off = (uint32_t)(n * SM_STRIDE + kp * 2) * 2;
            uint32_t idx = (uint32_t)((n * KPAD + k0) >> 1) + kp;
            *(uint32_t*)(smem + BH + off) = __ldg(bh32 + idx);
            *(uint32_t*)(smem + BL + off) = __ldg(bl32 + idx);
        }
        __syncthreads();

        #pragma unroll
        for (int ks = 0; ks < 4; ks++) {
            const int kk = ks * 16;
            uint32_t ah[4][4], al[4][4], bhf[4][2], blf[4][2];
            #pragma unroll
            for (int mt = 0; mt < 4; mt++) {
                uint32_t ea = (uint32_t)((wm * 64 + mt * 16 + a_r) * SM_STRIDE + kk + a_c) * 2;
                ldsm_x4(ah[mt][0], ah[mt][1], ah[mt][2], ah[mt][3], sbase + AH + ea);
                ldsm_x4(al[mt][0], al[mt][1], al[mt][2], al[mt][3], sbase + AL + ea);
            }
            #pragma unroll
            for (int pr = 0; pr < 2; pr++) {
                uint32_t eb = (uint32_t)((wn * 32 + pr * 16 + b_r) * SM_STRIDE + kk + b_c) * 2;
                ldsm_x4(bhf[2*pr][0], bhf[2*pr][1], bhf[2*pr+1][0], bhf[2*pr+1][1], sbase + BH + eb);
                ldsm_x4(blf[2*pr][0], blf[2*pr][1], blf[2*pr+1][0], blf[2*pr+1][1], sbase + BL + eb);
            }
            #pragma unroll
            for (int mt = 0; mt < 4; mt++)
                #pragma unroll
                for (int nt = 0; nt < 4; nt++) {
                    mma_bf16(acc[mt][nt], ah[mt], bhf[nt]);
                    mma_bf16(acc[mt][nt], ah[mt], blf[nt]);
                    mma_bf16(acc[mt][nt], al[mt], bhf[nt]);
                }
        }
    }

    // --- epilogue: * dinv[row] ---
    const int g = lane >> 2, q = lane & 3;
    #pragma unroll
    for (int mt = 0; mt < 4; mt++) {
        int r0 = mbase + wm * 64 + mt * 16 + g;
        int r1 = r0 + 8;
        float d0 = (r0 < N_NODES) ? g_dinv[r0] : 0.f;
        float d1 = (r1 < N_NODES) ? g_dinv[r1] : 0.f;
        #pragma unroll
        for (int nt = 0; nt < 4; nt++) {
            int col = wn * 32 + nt * 8 + q * 2;
            if (r0 < N_NODES) {
                float2 v = make_float2(acc[mt][nt][0] * d0, acc[mt][nt][1] * d0);
                *(float2*)(C + (size_t)r0 * HID_DIM + col) = v;
            }
            if (r1 < N_NODES) {
                float2 v = make_float2(acc[mt][nt][2] * d1, acc[mt][nt][3] * d1);
                *(float2*)(C + (size_t)r1 * HID_DIM + col) = v;
            }
        }
    }
}

// ---------------- SIMT GEMM (layer 2) with dinv epilogue ----------------
template <int BN>
__global__ __launch_bounds__(16 * (BN / 8))
void gemm_dinv_kernel(const float* __restrict__ A, const float* __restrict__ B,
                      float* __restrict__ C, int M, int K) {
    constexpr int BM = 128, BK = 16, TM = 8, TN = 8;
    constexpr int TX = BN / TN;
    constexpr int NT = TX * (BM / TM);

    __shared__ float As[BK][BM + 4];
    __shared__ float Bs[BK][BN];

    const int tid = threadIdx.x;
    const int block_row = blockIdx.x * BM;
    const int tx = tid % TX;
    const int ty = tid / TX;

    float acc[TM][TN] = {};

    for (int k0 = 0; k0 < K; k0 += BK) {
        #pragma unroll
        for (int idx = tid; idx < BM * BK; idx += NT) {
            int r = idx / BK, c = idx % BK;
            int gr = block_row + r, gc = k0 + c;
            float v = 0.f;
            if (gr < M && gc < K) v = A[(size_t)gr * K + gc];
            As[c][r] = v;
        }
        #pragma unroll
        for (int idx = tid; idx < BK * BN; idx += NT) {
            int r = idx / BN, c = idx % BN;
            int gr = k0 + r;
            Bs[r][c] = (gr < K) ? B[(size_t)gr * BN + c] : 0.f;
        }
        __syncthreads();
        #pragma unroll
        for (int k = 0; k < BK; k++) {
            float ra[TM], rb[TN];
            #pragma unroll
            for (int i = 0; i < TM; i++) ra[i] = As[k][ty * TM + i];
            #pragma unroll
            for (int j = 0; j < TN; j++) rb[j] = Bs[k][tx * TN + j];
            #pragma unroll
            for (int i = 0; i < TM; i++)
                #pragma unroll
                for (int j = 0; j < TN; j++)
                    acc[i][j] = fmaf(ra[i], rb[j], acc[i][j]);
        }
        __syncthreads();
    }
    #pragma unroll
    for (int i = 0; i < TM; i++) {
        int gr = block_row + ty * TM + i;
        if (gr < M) {
            float s = g_dinv[gr];
            #pragma unroll
            for (int j = 0; j < TN; j++)
                C[(size_t)gr * BN + tx * TN + j] = acc[i][j] * s;
        }
    }
}

// ---------------- CSR gather aggregation ----------------
template <int F, bool RELU>
__global__ __launch_bounds__(F)
void aggregate_kernel(const float* __restrict__ g, const float* __restrict__ bias,
                      float* __restrict__ out) {
    int node = blockIdx.x;
    int f = threadIdx.x;
    int start = g_rowptr[node];
    int end   = g_rowptr[node + 1];
    float s = g[(size_t)node * F + f];  // self loop
    int e = start;
    for (; e + 1 < end; e += 2) {
        int s0 = g_col[e], s1 = g_col[e + 1];
        s += __ldg(&g[(size_t)s0 * F + f]) + __ldg(&g[(size_t)s1 * F + f]);
    }
    if (e < end) s += __ldg(&g[(size_t)g_col[e] * F + f]);
    float v = g_dinv[node] * s + bias[f];
    if (RELU) v = fmaxf(v, 0.f);
    out[(size_t)node * F + f] = v;
}

// ---------------- launch ----------------
extern "C" void kernel_launch(void* const* d_in, const int* in_sizes, int n_in,
                              void* d_out, int out_size) {
    const float* x  = (const float*)d_in[0];
    const int*   ei = (const int*)  d_in[1];
    const float* W1 = (const float*)d_in[2];
    const float* b1 = (const float*)d_in[3];
    const float* W2 = (const float*)d_in[4];
    const float* b2 = (const float*)d_in[5];
    float* out = (float*)d_out;

    const int* src = ei;
    const int* dst = ei + N_EDGES;

    float *p_g1 = nullptr, *p_h1 = nullptr, *p_g2 = nullptr;
    cudaGetSymbolAddress((void**)&p_g1, g_g1);
    cudaGetSymbolAddress((void**)&p_h1, g_h1);
    cudaGetSymbolAddress((void**)&p_g2, g_g2);

    const int GEMM1_SMEM = 4 * 128 * SM_STRIDE * 2;  // 73728
    cudaFuncSetAttribute(gemm1_hmma, cudaFuncAttributeMaxDynamicSharedMemorySize, GEMM1_SMEM);

    // CSR build + degrees
    k_zero_indeg<<<(N_NODES + 255) / 256, 256>>>();
    k_hist<<<(N_EDGES + 511) / 512, 512>>>(dst);
    k_scan<<<1, 1024>>>();
    k_fill<<<(N_EDGES + 511) / 512, 512>>>(src, dst);

    // W1 -> transposed bf16 hi/lo
    k_convert_W<<<(HID_DIM * KPAD + 255) / 256, 256>>>(W1);

    const int mblocks = (N_NODES + 127) / 128;

    // layer 1: HMMA GEMM + aggregate
    gemm1_hmma<<<mblocks, 256, GEMM1_SMEM>>>(x, p_g1);
    aggregate_kernel<HID_DIM, true><<<N_NODES, HID_DIM>>>(p_g1, b1, p_h1);

    // layer 2: SIMT GEMM + aggregate
    gemm_dinv_kernel<EMB_DIM><<<mblocks, 128>>>(p_h1, W2, p_g2, N_NODES, HID_DIM);
    aggregate_kernel<EMB_DIM, false><<<N_NODES, EMB_DIM>>>(p_g2, b2, out);
}

// round 5
// speedup vs baseline: 1.9337x; 1.6553x over previous
#include <cuda_runtime.h>
#include <cuda_bf16.h>
#include <cstdint>

#define N_NODES 100000
#define N_EDGES 1600000
#define IN_DIM 1433
#define HID_DIM 128
#define EMB_DIM 64
#define KPAD 1472          // 23 * 64
#define KCHUNKS 23

// ---------------- scratch (static device globals; no cudaMalloc allowed) ----------------
__device__ float g_g1[(size_t)N_NODES * HID_DIM];
__device__ __nv_bfloat16 g_h1h[(size_t)N_NODES * HID_DIM];
__device__ __nv_bfloat16 g_h1l[(size_t)N_NODES * HID_DIM];
__device__ float g_g2[(size_t)N_NODES * EMB_DIM];
__device__ int   g_indeg[N_NODES];
__device__ int   g_rowptr[N_NODES + 1];
__device__ int   g_cursor[N_NODES];
__device__ int   g_col[N_EDGES];
__device__ float g_dinv[N_NODES];
__device__ __nv_bfloat16 g_Wt_hi[HID_DIM * KPAD];    // W1^T split-high, [128][KPAD]
__device__ __nv_bfloat16 g_Wt_lo[HID_DIM * KPAD];
__device__ __nv_bfloat16 g_W2t_hi[EMB_DIM * HID_DIM]; // W2^T split-high, [64][128]
__device__ __nv_bfloat16 g_W2t_lo[EMB_DIM * HID_DIM];

// ---------------- portable PTX helpers ----------------
__device__ __forceinline__ uint32_t smem_u32(const void* p) {
    uint32_t a;
    asm("{ .reg .u64 t; cvta.to.shared.u64 t, %1; cvt.u32.u64 %0, t; }" : "=r"(a) : "l"(p));
    return a;
}
__device__ __forceinline__ void ldsm_x4(uint32_t& r0, uint32_t& r1, uint32_t& r2, uint32_t& r3,
                                        uint32_t addr) {
    asm volatile("ldmatrix.sync.aligned.m8n8.x4.shared.b16 {%0,%1,%2,%3}, [%4];"
                 : "=r"(r0), "=r"(r1), "=r"(r2), "=r"(r3) : "r"(addr));
}
__device__ __forceinline__ void mma_bf16(float* d, const uint32_t* a, const uint32_t* b) {
    asm volatile(
        "mma.sync.aligned.m16n8k16.row.col.f32.bf16.bf16.f32 "
        "{%0,%1,%2,%3}, {%4,%5,%6,%7}, {%8,%9}, {%0,%1,%2,%3};"
        : "+f"(d[0]), "+f"(d[1]), "+f"(d[2]), "+f"(d[3])
        : "r"(a[0]), "r"(a[1]), "r"(a[2]), "r"(a[3]), "r"(b[0]), "r"(b[1]));
}
__device__ __forceinline__ void cp16(uint32_t dst, const void* src, bool valid) {
    int sz = valid ? 16 : 0;
    asm volatile("cp.async.cg.shared.global [%0], [%1], 16, %2;"
                 :: "r"(dst), "l"(src), "r"(sz) : "memory");
}
__device__ __forceinline__ void cp4(uint32_t dst, const void* src, bool valid) {
    int sz = valid ? 4 : 0;
    asm volatile("cp.async.ca.shared.global [%0], [%1], 4, %2;"
                 :: "r"(dst), "l"(src), "r"(sz) : "memory");
}
__device__ __forceinline__ void cp_commit() { asm volatile("cp.async.commit_group;" ::: "memory"); }
__device__ __forceinline__ void cp_wait_all() { asm volatile("cp.async.wait_group 0;" ::: "memory"); }

// ---------------- CSR build ----------------
__global__ void k_zero_indeg() {
    int i = blockIdx.x * blockDim.x + threadIdx.x;
    if (i < N_NODES) g_indeg[i] = 0;
}
__global__ void k_hist(const int* __restrict__ dst) {
    int e = blockIdx.x * blockDim.x + threadIdx.x;
    if (e < N_EDGES) atomicAdd(&g_indeg[dst[e]], 1);
}
// single-block shfl scan
__global__ void k_scan() {
    __shared__ int wsum[32];
    __shared__ int s_carry;
    const int tid = threadIdx.x, lane = tid & 31, wid = tid >> 5;
    if (tid == 0) s_carry = 0;
    __syncthreads();
    for (int base = 0; base < N_NODES; base += 1024) {
        int i = base + tid;
        int v = (i < N_NODES) ? g_indeg[i] : 0;
        int x = v;
        #pragma unroll
        for (int off = 1; off < 32; off <<= 1) {
            int t = __shfl_up_sync(0xFFFFFFFF, x, off);
            if (lane >= off) x += t;
        }
        if (lane == 31) wsum[wid] = x;
        __syncthreads();
        if (wid == 0) {
            int w = wsum[lane];
            #pragma unroll
            for (int off = 1; off < 32; off <<= 1) {
                int t = __shfl_up_sync(0xFFFFFFFF, w, off);
                if (lane >= off) w += t;
            }
            wsum[lane] = w;
        }
        __syncthreads();
        int incl = x + (wid > 0 ? wsum[wid - 1] : 0) + s_carry;
        if (i < N_NODES) {
            int rp = incl - v;
            g_rowptr[i] = rp;
            g_cursor[i] = rp;
            g_dinv[i]   = rsqrtf((float)(v + 1));
        }
        __syncthreads();
        if (tid == 0) s_carry += wsum[31];
        __syncthreads();
    }
    if (tid == 0) g_rowptr[N_NODES] = N_EDGES;
}
__global__ void k_fill(const int* __restrict__ src, const int* __restrict__ dst) {
    int e = blockIdx.x * blockDim.x + threadIdx.x;
    if (e < N_EDGES) {
        int pos = atomicAdd(&g_cursor[dst[e]], 1);
        g_col[pos] = src[e];
    }
}

// ---------------- weight transpose + bf16 split ----------------
__global__ void k_convert_W(const float* __restrict__ W1) {
    int idx = blockIdx.x * blockDim.x + threadIdx.x;
    if (idx < HID_DIM * KPAD) {
        int n = idx / KPAD, k = idx % KPAD;
        float v = (k < IN_DIM) ? W1[(size_t)k * HID_DIM + n] : 0.f;
        __nv_bfloat16 h = __float2bfloat16(v);
        g_Wt_hi[idx] = h;
        g_Wt_lo[idx] = __float2bfloat16(v - __bfloat162float(h));
    }
}
__global__ void k_convert_W2(const float* __restrict__ W2) {
    int idx = blockIdx.x * blockDim.x + threadIdx.x;
    if (idx < EMB_DIM * HID_DIM) {
        int n = idx / HID_DIM, k = idx % HID_DIM;
        float v = W2[(size_t)k * EMB_DIM + n];
        __nv_bfloat16 h = __float2bfloat16(v);
        g_W2t_hi[idx] = h;
        g_W2t_lo[idx] = __float2bfloat16(v - __bfloat162float(h));
    }
}

// ---------------- GEMM1: C[M x 128] = (X @ W1) * dinv[row] (pipelined HMMA) ----------------
#define SM_STRIDE 72   // bf16 elems per row (144B): conflict-free ldmatrix
// smem layout (bytes)
#define G1_XF0 0
#define G1_XF1 32768
#define G1_AH  65536
#define G1_AL  83968
#define G1_B0  102400           /* BH stage0 */
#define G1_BSTG 18432
#define G1_BL0 (G1_B0 + 2 * G1_BSTG)
#define G1_SMEM (G1_BL0 + 2 * G1_BSTG)   /* 176128 */

__global__ __launch_bounds__(256)
void gemm1_hmma(const float* __restrict__ X, float* __restrict__ C) {
    extern __shared__ char smem[];
    const uint32_t sbase = smem_u32(smem);
    const int tid = threadIdx.x, lane = tid & 31, wid = tid >> 5;
    const int wm = wid >> 2, wn = wid & 3;
    const int mbase = blockIdx.x * 128;

    const int a_r = (lane & 15), a_c = ((lane & 16) >> 1);
    const int b_r = ((lane & 16) >> 1) + (lane & 7), b_c = (lane & 8);

    float acc[4][4][4];
    #pragma unroll
    for (int i = 0; i < 4; i++)
        #pragma unroll
        for (int j = 0; j < 4; j++)
            #pragma unroll
            for (int v = 0; v < 4; v++) acc[i][j][v] = 0.f;

    // ---- async load issue for chunk kc into stage buf ----
    auto issue = [&](int kc, int buf) {
        const int k0 = kc * 64;
        // X fp32 tile 128x64 -> XF[buf] (4B ops; X rows not 16B aligned)
        uint32_t xdst = sbase + (buf ? G1_XF1 : G1_XF0);
        #pragma unroll
        for (int i = tid; i < 8192; i += 256) {
            int r = i >> 6, kp = i & 63;
            int gr = mbase + r, gk = k0 + kp;
            cp4(xdst + (uint32_t)i * 4, X + (size_t)gr * IN_DIM + gk,
                (gr < N_NODES) && (gk < IN_DIM));
        }
        // W1 split tiles 128x64 bf16 -> BH[buf], BL[buf] (16B ops)
        uint32_t bh = sbase + G1_B0 + buf * G1_BSTG;
        uint32_t bl = sbase + G1_BL0 + buf * G1_BSTG;
        #pragma unroll
        for (int i = tid; i < 1024; i += 256) {
            int n = i >> 3, c8 = (i & 7) * 8;
            uint32_t doff = (uint32_t)(n * SM_STRIDE + c8) * 2;
            size_t soff = (size_t)n * KPAD + k0 + c8;
            cp16(bh + doff, g_Wt_hi + soff, true);
            cp16(bl + doff, g_Wt_lo + soff, true);
        }
    };

    issue(0, 0);
    cp_commit();

    for (int kc = 0; kc < KCHUNKS; kc++) {
        const int buf = kc & 1;
        cp_wait_all();          // chunk kc arrived (only pending group)
        __syncthreads();        // all threads done with prev mma + see XF[buf]
        if (kc + 1 < KCHUNKS) { issue(kc + 1, buf ^ 1); cp_commit(); }

        // ---- split fp32 -> hi/lo bf16 (smem -> smem) ----
        {
            const float4* xf = (const float4*)(smem + (buf ? G1_XF1 : G1_XF0));
            #pragma unroll
            for (int i = tid; i < 2048; i += 256) {
                float4 v = xf[i];
                int r = i >> 4, kp4 = (i & 15) * 4;
                __nv_bfloat16 h0 = __float2bfloat16(v.x), h1 = __float2bfloat16(v.y);
                __nv_bfloat16 h2 = __float2bfloat16(v.z), h3 = __float2bfloat16(v.w);
                __nv_bfloat16 l0 = __float2bfloat16(v.x - __bfloat162float(h0));
                __nv_bfloat16 l1 = __float2bfloat16(v.y - __bfloat162float(h1));
                __nv_bfloat16 l2 = __float2bfloat16(v.z - __bfloat162float(h2));
                __nv_bfloat16 l3 = __float2bfloat16(v.w - __bfloat162float(h3));
                uint32_t off = (uint32_t)(r * SM_STRIDE + kp4) * 2;
                __nv_bfloat162 hv0; hv0.x = h0; hv0.y = h1;
                __nv_bfloat162 hv1; hv1.x = h2; hv1.y = h3;
                __nv_bfloat162 lv0; lv0.x = l0; lv0.y = l1;
                __nv_bfloat162 lv1; lv1.x = l2; lv1.y = l3;
                *(uint2*)(smem + G1_AH + off) = make_uint2(
                    *(uint32_t*)&hv0, *(uint32_t*)&hv1);
                *(uint2*)(smem + G1_AL + off) = make_uint2(
                    *(uint32_t*)&lv0, *(uint32_t*)&lv1);
            }
        }
        __syncthreads();

        const uint32_t BH = sbase + G1_B0 + buf * G1_BSTG;
        const uint32_t BL = sbase + G1_BL0 + buf * G1_BSTG;
        #pragma unroll
        for (int ks = 0; ks < 4; ks++) {
            const int kk = ks * 16;
            uint32_t ah[4][4], al[4][4], bhf[4][2], blf[4][2];
            #pragma unroll
            for (int mt = 0; mt < 4; mt++) {
                uint32_t ea = (uint32_t)((wm * 64 + mt * 16 + a_r) * SM_STRIDE + kk + a_c) * 2;
                ldsm_x4(ah[mt][0], ah[mt][1], ah[mt][2], ah[mt][3], sbase + G1_AH + ea);
                ldsm_x4(al[mt][0], al[mt][1], al[mt][2], al[mt][3], sbase + G1_AL + ea);
            }
            #pragma unroll
            for (int pr = 0; pr < 2; pr++) {
                uint32_t eb = (uint32_t)((wn * 32 + pr * 16 + b_r) * SM_STRIDE + kk + b_c) * 2;
                ldsm_x4(bhf[2*pr][0], bhf[2*pr][1], bhf[2*pr+1][0], bhf[2*pr+1][1], BH + eb);
                ldsm_x4(blf[2*pr][0], blf[2*pr][1], blf[2*pr+1][0], blf[2*pr+1][1], BL + eb);
            }
            #pragma unroll
            for (int mt = 0; mt < 4; mt++)
                #pragma unroll
                for (int nt = 0; nt < 4; nt++) {
                    mma_bf16(acc[mt][nt], ah[mt], bhf[nt]);
                    mma_bf16(acc[mt][nt], ah[mt], blf[nt]);
                    mma_bf16(acc[mt][nt], al[mt], bhf[nt]);
                }
        }
        __syncthreads();   // mma reads done before buffers are overwritten
    }

    const int g = lane >> 2, q = lane & 3;
    #pragma unroll
    for (int mt = 0; mt < 4; mt++) {
        int r0 = mbase + wm * 64 + mt * 16 + g;
        int r1 = r0 + 8;
        float d0 = (r0 < N_NODES) ? g_dinv[r0] : 0.f;
        float d1 = (r1 < N_NODES) ? g_dinv[r1] : 0.f;
        #pragma unroll
        for (int nt = 0; nt < 4; nt++) {
            int col = wn * 32 + nt * 8 + q * 2;
            if (r0 < N_NODES)
                *(float2*)(C + (size_t)r0 * HID_DIM + col) =
                    make_float2(acc[mt][nt][0] * d0, acc[mt][nt][1] * d0);
            if (r1 < N_NODES)
                *(float2*)(C + (size_t)r1 * HID_DIM + col) =
                    make_float2(acc[mt][nt][2] * d1, acc[mt][nt][3] * d1);
        }
    }
}

// ---------------- GEMM2: g2[M x 64] = (h1 @ W2) * dinv[row] (HMMA, K=128 single tile) ----------------
#define SM2_STRIDE 136   // 128 data + 8 pad elems (272B rows, odd*16B)
#define G2_AH 0
#define G2_AL (128 * SM2_STRIDE * 2)
#define G2_BH (2 * 128 * SM2_STRIDE * 2)
#define G2_BL (G2_BH + 64 * SM2_STRIDE * 2)
#define G2_SMEM (G2_BL + 64 * SM2_STRIDE * 2)   /* 104448 */

__global__ __launch_bounds__(256)
void gemm2_hmma(float* __restrict__ C) {
    extern __shared__ char smem[];
    const uint32_t sbase = smem_u32(smem);
    const int tid = threadIdx.x, lane = tid & 31, wid = tid >> 5;
    const int wm = wid >> 1, wn = wid & 1;   // 4 x 2 warps, warp tile 32x32
    const int mbase = blockIdx.x * 128;

    const int a_r = (lane & 15), a_c = ((lane & 16) >> 1);
    const int b_r = ((lane & 16) >> 1) + (lane & 7), b_c = (lane & 8);

    // load A (h1 split) 128x128 and B (W2 split) 64x128
    #pragma unroll
    for (int i = tid; i < 2048; i += 256) {
        int r = i >> 4, c8 = (i & 15) * 8;
        int gr = mbase + r;
        bool ok = gr < N_NODES;
        uint32_t doff = (uint32_t)(r * SM2_STRIDE + c8) * 2;
        size_t soff = (size_t)gr * HID_DIM + c8;
        cp16(sbase + G2_AH + doff, g_h1h + soff, ok);
        cp16(sbase + G2_AL + doff, g_h1l + soff, ok);
    }
    #pragma unroll
    for (int i = tid; i < 1024; i += 256) {
        int n = i >> 4, c8 = (i & 15) * 8;
        uint32_t doff = (uint32_t)(n * SM2_STRIDE + c8) * 2;
        size_t soff = (size_t)n * HID_DIM + c8;
        cp16(sbase + G2_BH + doff, g_W2t_hi + soff, true);
        cp16(sbase + G2_BL + doff, g_W2t_lo + soff, true);
    }
    cp_commit();
    cp_wait_all();
    __syncthreads();

    float acc[2][4][4];
    #pragma unroll
    for (int i = 0; i < 2; i++)
        #pragma unroll
        for (int j = 0; j < 4; j++)
            #pragma unroll
            for (int v = 0; v < 4; v++) acc[i][j][v] = 0.f;

    #pragma unroll
    for (int ks = 0; ks < 8; ks++) {
        const int kk = ks * 16;
        uint32_t ah[2][4], al[2][4], bhf[4][2], blf[4][2];
        #pragma unroll
        for (int mt = 0; mt < 2; mt++) {
            uint32_t ea = (uint32_t)((wm * 32 + mt * 16 + a_r) * SM2_STRIDE + kk + a_c) * 2;
            ldsm_x4(ah[mt][0], ah[mt][1], ah[mt][2], ah[mt][3], sbase + G2_AH + ea);
            ldsm_x4(al[mt][0], al[mt][1], al[mt][2], al[mt][3], sbase + G2_AL + ea);
        }
        #pragma unroll
        for (int pr = 0; pr < 2; pr++) {
            uint32_t eb = (uint32_t)((wn * 32 + pr * 16 + b_r) * SM2_STRIDE + kk + b_c) * 2;
            ldsm_x4(bhf[2*pr][0], bhf[2*pr][1], bhf[2*pr+1][0], bhf[2*pr+1][1], sbase + G2_BH + eb);
            ldsm_x4(blf[2*pr][0], blf[2*pr][1], blf[2*pr+1][0], blf[2*pr+1][1], sbase + G2_BL + eb);
        }
        #pragma unroll
        for (int mt = 0; mt < 2; mt++)
            #pragma unroll
            for (int nt = 0; nt < 4; nt++) {
                mma_bf16(acc[mt][nt], ah[mt], bhf[nt]);
                mma_bf16(acc[mt][nt], ah[mt], blf[nt]);
                mma_bf16(acc[mt][nt], al[mt], bhf[nt]);
            }
    }

    const int g = lane >> 2, q = lane & 3;
    #pragma unroll
    for (int mt = 0; mt < 2; mt++) {
        int r0 = mbase + wm * 32 + mt * 16 + g;
        int r1 = r0 + 8;
        float d0 = (r0 < N_NODES) ? g_dinv[r0] : 0.f;
        float d1 = (r1 < N_NODES) ? g_dinv[r1] : 0.f;
        #pragma unroll
        for (int nt = 0; nt < 4; nt++) {
            int col = wn * 32 + nt * 8 + q * 2;
            if (r0 < N_NODES)
                *(float2*)(C + (size_t)r0 * EMB_DIM + col) =
                    make_float2(acc[mt][nt][0] * d0, acc[mt][nt][1] * d0);
            if (r1 < N_NODES)
                *(float2*)(C + (size_t)r1 * EMB_DIM + col) =
                    make_float2(acc[mt][nt][2] * d1, acc[mt][nt][3] * d1);
        }
    }
}

// ---------------- CSR gather aggregation ----------------
// layer 1: out = relu(dinv*(gather+self) + b) -> split bf16 h1h/h1l
__global__ __launch_bounds__(HID_DIM)
void aggregate1(const float* __restrict__ g, const float* __restrict__ bias) {
    int node = blockIdx.x;
    int f = threadIdx.x;
    int start = g_rowptr[node];
    int end   = g_rowptr[node + 1];
    float s = g[(size_t)node * HID_DIM + f];
    int e = start;
    for (; e + 1 < end; e += 2) {
        int s0 = g_col[e], s1 = g_col[e + 1];
        s += __ldg(&g[(size_t)s0 * HID_DIM + f]) + __ldg(&g[(size_t)s1 * HID_DIM + f]);
    }
    if (e < end) s += __ldg(&g[(size_t)g_col[e] * HID_DIM + f]);
    float v = fmaxf(g_dinv[node] * s + bias[f], 0.f);
    __nv_bfloat16 h = __float2bfloat16(v);
    size_t o = (size_t)node * HID_DIM + f;
    g_h1h[o] = h;
    g_h1l[o] = __float2bfloat16(v - __bfloat162float(h));
}
// layer 2: out = dinv*(gather+self) + b (fp32)
__global__ __launch_bounds__(EMB_DIM)
void aggregate2(const float* __restrict__ g, const float* __restrict__ bias,
                float* __restrict__ out) {
    int node = blockIdx.x;
    int f = threadIdx.x;
    int start = g_rowptr[node];
    int end   = g_rowptr[node + 1];
    float s = g[(size_t)node * EMB_DIM + f];
    int e = start;
    for (; e + 1 < end; e += 2) {
        int s0 = g_col[e], s1 = g_col[e + 1];
        s += __ldg(&g[(size_t)s0 * EMB_DIM + f]) + __ldg(&g[(size_t)s1 * EMB_DIM + f]);
    }
    if (e < end) s += __ldg(&g[(size_t)g_col[e] * EMB_DIM + f]);
    out[(size_t)node * EMB_DIM + f] = g_dinv[node] * s + bias[f];
}

// ---------------- launch ----------------
extern "C" void kernel_launch(void* const* d_in, const int* in_sizes, int n_in,
                              void* d_out, int out_size) {
    const float* x  = (const float*)d_in[0];
    const int*   ei = (const int*)  d_in[1];
    const float* W1 = (const float*)d_in[2];
    const float* b1 = (const float*)d_in[3];
    const float* W2 = (const float*)d_in[4];
    const float* b2 = (const float*)d_in[5];
    float* out = (float*)d_out;

    const int* src = ei;
    const int* dst = ei + N_EDGES;

    float *p_g1 = nullptr, *p_g2 = nullptr;
    cudaGetSymbolAddress((void**)&p_g1, g_g1);
    cudaGetSymbolAddress((void**)&p_g2, g_g2);

    static bool attr_done = false;
    if (!attr_done) {
        cudaFuncSetAttribute(gemm1_hmma, cudaFuncAttributeMaxDynamicSharedMemorySize, G1_SMEM);
        cudaFuncSetAttribute(gemm2_hmma, cudaFuncAttributeMaxDynamicSharedMemorySize, G2_SMEM);
        attr_done = true;
    }

    // CSR build + degrees
    k_zero_indeg<<<(N_NODES + 255) / 256, 256>>>();
    k_hist<<<(N_EDGES + 511) / 512, 512>>>(dst);
    k_scan<<<1, 1024>>>();
    k_fill<<<(N_EDGES + 511) / 512, 512>>>(src, dst);

    // weights -> transposed bf16 hi/lo
    k_convert_W<<<(HID_DIM * KPAD + 255) / 256, 256>>>(W1);
    k_convert_W2<<<(EMB_DIM * HID_DIM + 255) / 256, 256>>>(W2);

    const int mblocks = (N_NODES + 127) / 128;

    gemm1_hmma<<<mblocks, 256, G1_SMEM>>>(x, p_g1);
    aggregate1<<<N_NODES, HID_DIM>>>(p_g1, b1);
    gemm2_hmma<<<mblocks, 256, G2_SMEM>>>(p_g2);
    aggregate2<<<N_NODES, EMB_DIM>>>(p_g2, b2, out);
}